// round 16
// baseline (speedup 1.0000x reference)
#include <cuda_runtime.h>
#include <cstdint>

// soft_to_hard_quantize via fp16 tensor cores (mma.m16n8k16).
// R16 vs R15: double-buffered cp.async staging of the x stream. The persistent
// loop prefetches chunk i+2*NBLK into smem while computing chunk i, replacing
// the loop-head LDG long-scoreboard stall (~600-900cyc/warp/iter) with a
// wait on a transfer issued a full iteration earlier. x fragments now come
// from conflict-free LDS.128 (64B row stride; each 8-lane phase = 128
// contiguous bytes). Math identical to R13..R15.
//
// logit[v][m] = 14.4269504*dot(x_v, r_m) - 7.2134752*||r_m||^2   (log2 domain)
// e = exp2(logit - rowmax);  z_v = sum_m e*r_m / sum_m e

#define TPB    128    // 4 warps/block, 2 tiles (32 vectors) per warp-iteration
#define DVEC   16
#define NCHUNK 4096   // tile-pair chunks (each chunk = 128 vectors = 8KB)
#define NBLK   760    // 152 SMs x 5 CTAs -> one resident wave
#define CHUNK_FLOATS 2048   // 128 vectors * 16 floats

__device__ __forceinline__ uint32_t pkhf(float lo_elem, float hi_elem) {
    uint32_t r;
    asm("cvt.rn.f16x2.f32 %0, %1, %2;" : "=r"(r) : "f"(hi_elem), "f"(lo_elem));
    return r;
}
__device__ __forceinline__ float hf0(uint32_t u) {
    float f;
    asm("{ .reg .b16 l, h; mov.b32 {l, h}, %1; cvt.f32.f16 %0, l; }" : "=f"(f) : "r"(u));
    return f;
}
__device__ __forceinline__ float hf1(uint32_t u) {
    float f;
    asm("{ .reg .b16 l, h; mov.b32 {l, h}, %1; cvt.f32.f16 %0, h; }" : "=f"(f) : "r"(u));
    return f;
}
__device__ __forceinline__ float ex2f(float x) {
    float r; asm("ex2.approx.ftz.f32 %0, %1;" : "=f"(r) : "f"(x)); return r;
}
__device__ __forceinline__ float rcpf(float x) {
    float r; asm("rcp.approx.ftz.f32 %0, %1;" : "=f"(r) : "f"(x)); return r;
}
__device__ __forceinline__ void mma16(float c[4],
                                      uint32_t a0, uint32_t a1, uint32_t a2, uint32_t a3,
                                      uint32_t b0, uint32_t b1) {
    asm volatile(
        "mma.sync.aligned.m16n8k16.row.col.f32.f16.f16.f32 "
        "{%0,%1,%2,%3}, {%4,%5,%6,%7}, {%8,%9}, {%0,%1,%2,%3};"
        : "+f"(c[0]), "+f"(c[1]), "+f"(c[2]), "+f"(c[3])
        : "r"(a0), "r"(a1), "r"(a2), "r"(a3), "r"(b0), "r"(b1));
}
__device__ __forceinline__ uint4 split4(float v0, float v1, float v2, float v3) {
    uint4 r;
    r.x = pkhf(v0, v1);
    r.y = pkhf(v2, v3);
    r.z = pkhf(v0 - hf0(r.x), v1 - hf1(r.x));
    r.w = pkhf(v2 - hf0(r.y), v3 - hf1(r.y));
    return r;
}
__device__ __forceinline__ void cpasync16(uint32_t saddr, const void* g) {
    asm volatile("cp.async.ca.shared.global [%0], [%1], 16;" :: "r"(saddr), "l"(g));
}

__global__ __launch_bounds__(TPB, 5)
void stq_kernel(const float* __restrict__ x,
                const float* __restrict__ ref,
                float* __restrict__ out) {
    // Codebook tables (built once per persistent block) + double x buffer.
    __shared__ __align__(16) uint4 sP1[256];
    __shared__ __align__(16) uint4 sPB[256];
    __shared__ float2 sB2[32];
    __shared__ __align__(16) float sX[2 * CHUNK_FLOATS];   // 2 x 8KB

    const int tid = threadIdx.x;

    #pragma unroll
    for (int i = tid; i < 256; i += TPB) {
        {   // pass-1 entry (m, qq): k-slots {2q,2q+1,2q+8,2q+9} <- phys {4q..4q+3}
            const int m = i >> 2, qq = i & 3;
            const float S = 14.426950408889634f;   // 10*log2(e)
            const float4 b = *reinterpret_cast<const float4*>(ref + m * DVEC + 4 * qq);
            sP1[i] = split4(S * b.x, S * b.y, S * b.z, S * b.w);
        }
        {   // pass-2 entry (s, nt, gg, qq): output col J(g,nt)=4*(g>>1)+2*nt+(g&1)
            const int qq = i & 3, gg = (i >> 2) & 7, nt = (i >> 5) & 1, s = i >> 6;
            const int j = 4 * (gg >> 1) + 2 * nt + (gg & 1);
            sPB[i] = split4(ref[(16 * s + 2 * qq) * DVEC + j],
                            ref[(16 * s + 2 * qq + 1) * DVEC + j],
                            ref[(16 * s + 2 * qq + 8) * DVEC + j],
                            ref[(16 * s + 2 * qq + 9) * DVEC + j]);
        }
    }
    if (tid < 32) {  // bias pairs (t, qq)
        const int t = tid >> 2, qq = tid & 3;
        const int m0 = 8 * t + 2 * qq, m1 = m0 + 1;
        float s0 = 0.0f, s1 = 0.0f;
        #pragma unroll
        for (int i = 0; i < DVEC; i += 4) {
            const float4 a = *reinterpret_cast<const float4*>(ref + m0 * DVEC + i);
            const float4 b = *reinterpret_cast<const float4*>(ref + m1 * DVEC + i);
            s0 = fmaf(a.x, a.x, fmaf(a.y, a.y, fmaf(a.z, a.z, fmaf(a.w, a.w, s0))));
            s1 = fmaf(b.x, b.x, fmaf(b.y, b.y, fmaf(b.z, b.z, fmaf(b.w, b.w, s1))));
        }
        sB2[tid] = make_float2(-7.2134752044448169f * s0,
                               -7.2134752044448169f * s1);
    }

    // ---- prologue: prefetch chunks bid and bid+NBLK ----
    const uint32_t sx0 = (uint32_t)__cvta_generic_to_shared(sX) + tid * 64u;
    const uint32_t sx1 = sx0 + CHUNK_FLOATS * 4u;
    {
        const float* g0 = x + (size_t)blockIdx.x * CHUNK_FLOATS + tid * 16;
        #pragma unroll
        for (int k = 0; k < 4; k++) cpasync16(sx0 + 16u * k, g0 + 4 * k);
        asm volatile("cp.async.commit_group;");
        const int c1 = blockIdx.x + NBLK;
        if (c1 < NCHUNK) {
            const float* g1 = x + (size_t)c1 * CHUNK_FLOATS + tid * 16;
            #pragma unroll
            for (int k = 0; k < 4; k++) cpasync16(sx1 + 16u * k, g1 + 4 * k);
        }
        asm volatile("cp.async.commit_group;");
    }
    __syncthreads();

    const int warp = tid >> 5;
    const int lane = tid & 31;
    const int g = lane >> 2;     // groupID
    const int q = lane & 3;      // threadID in group
    const int base = lane & 28;
    const uint32_t onesb = (g == 0) ? 0x3C003C00u : 0u;   // fp16 1.0 pair, n=0 col

    // local vector rows within a chunk (warp owns 32 vectors)
    const int lA  = warp * 32 + g;

    int it = 0;
    for (int chunk = blockIdx.x; chunk < NCHUNK; chunk += NBLK, it ^= 1) {
        // ---- wait for this chunk's staged copy (all but newest group) ----
        asm volatile("cp.async.wait_group 1;");
        __syncthreads();

        const float4* xb = reinterpret_cast<const float4*>(sX + it * CHUNK_FLOATS);

        // ---- fragment loads from smem (conflict-free LDS.128) + fp16 split ----
        uint32_t ahA[4], alA[4], ahB[4], alB[4];
        {
            const float4 fA0 = xb[(lA)      * 4 + q];
            const float4 fA1 = xb[(lA + 8)  * 4 + q];
            const float4 fB0 = xb[(lA + 16) * 4 + q];
            const float4 fB1 = xb[(lA + 24) * 4 + q];
            ahA[0] = pkhf(fA0.x, fA0.y); alA[0] = pkhf(fA0.x - hf0(ahA[0]), fA0.y - hf1(ahA[0]));
            ahA[2] = pkhf(fA0.z, fA0.w); alA[2] = pkhf(fA0.z - hf0(ahA[2]), fA0.w - hf1(ahA[2]));
            ahA[1] = pkhf(fA1.x, fA1.y); alA[1] = pkhf(fA1.x - hf0(ahA[1]), fA1.y - hf1(ahA[1]));
            ahA[3] = pkhf(fA1.z, fA1.w); alA[3] = pkhf(fA1.z - hf0(ahA[3]), fA1.w - hf1(ahA[3]));
            ahB[0] = pkhf(fB0.x, fB0.y); alB[0] = pkhf(fB0.x - hf0(ahB[0]), fB0.y - hf1(ahB[0]));
            ahB[2] = pkhf(fB0.z, fB0.w); alB[2] = pkhf(fB0.z - hf0(ahB[2]), fB0.w - hf1(ahB[2]));
            ahB[1] = pkhf(fB1.x, fB1.y); alB[1] = pkhf(fB1.x - hf0(ahB[1]), fB1.y - hf1(ahB[1]));
            ahB[3] = pkhf(fB1.z, fB1.w); alB[3] = pkhf(fB1.z - hf0(ahB[3]), fB1.w - hf1(ahB[3]));
        }
        __syncthreads();   // whole block done READING this buffer

        // ---- issue prefetch for chunk+2*NBLK into the buffer just consumed ----
        {
            const int nc = chunk + 2 * NBLK;
            if (nc < NCHUNK) {
                const uint32_t sdst = (it == 0) ? sx0 : sx1;
                const float* gsrc = x + (size_t)nc * CHUNK_FLOATS + tid * 16;
                #pragma unroll
                for (int k = 0; k < 4; k++) cpasync16(sdst + 16u * k, gsrc + 4 * k);
            }
            asm volatile("cp.async.commit_group;");   // commit even if empty
        }

        // ---- Pass 1: logits; bias pre-loaded into accumulators ----
        float cA[8][4], cB[8][4];
        #pragma unroll
        for (int t = 0; t < 8; t++) {
            float2 bb = sB2[t * 4 + q];
            cA[t][0] = bb.x; cA[t][1] = bb.y; cA[t][2] = bb.x; cA[t][3] = bb.y;
            cB[t][0] = bb.x; cB[t][1] = bb.y; cB[t][2] = bb.x; cB[t][3] = bb.y;
        }
        #pragma unroll
        for (int t = 0; t < 8; t++) {
            uint4 P = sP1[(8 * t + g) * 4 + q];
            mma16(cA[t], ahA[0], ahA[1], ahA[2], ahA[3], P.x, P.y);
            mma16(cA[t], ahA[0], ahA[1], ahA[2], ahA[3], P.z, P.w);
            mma16(cA[t], alA[0], alA[1], alA[2], alA[3], P.x, P.y);
            mma16(cB[t], ahB[0], ahB[1], ahB[2], ahB[3], P.x, P.y);
            mma16(cB[t], ahB[0], ahB[1], ahB[2], ahB[3], P.z, P.w);
            mma16(cB[t], alB[0], alB[1], alB[2], alB[3], P.x, P.y);
        }

        // ---- row maxes ----
        float mgA = fmaxf(cA[0][0], cA[0][1]), m8A = fmaxf(cA[0][2], cA[0][3]);
        float mgB = fmaxf(cB[0][0], cB[0][1]), m8B = fmaxf(cB[0][2], cB[0][3]);
        #pragma unroll
        for (int t = 1; t < 8; t++) {
            mgA = fmaxf(mgA, fmaxf(cA[t][0], cA[t][1]));
            m8A = fmaxf(m8A, fmaxf(cA[t][2], cA[t][3]));
            mgB = fmaxf(mgB, fmaxf(cB[t][0], cB[t][1]));
            m8B = fmaxf(m8B, fmaxf(cB[t][2], cB[t][3]));
        }
        mgA = fmaxf(mgA, __shfl_xor_sync(0xffffffffu, mgA, 1));
        mgA = fmaxf(mgA, __shfl_xor_sync(0xffffffffu, mgA, 2));
        m8A = fmaxf(m8A, __shfl_xor_sync(0xffffffffu, m8A, 1));
        m8A = fmaxf(m8A, __shfl_xor_sync(0xffffffffu, m8A, 2));
        mgB = fmaxf(mgB, __shfl_xor_sync(0xffffffffu, mgB, 1));
        mgB = fmaxf(mgB, __shfl_xor_sync(0xffffffffu, mgB, 2));
        m8B = fmaxf(m8B, __shfl_xor_sync(0xffffffffu, m8B, 1));
        m8B = fmaxf(m8B, __shfl_xor_sync(0xffffffffu, m8B, 2));

        // ---- Pass 2: exp -> fp16 ONCE; z MMAs + ones-column denominator ----
        float zA[2][4], zB[2][4], wA[4], wB[4];
        #pragma unroll
        for (int nt = 0; nt < 2; nt++) {
            zA[nt][0] = zA[nt][1] = zA[nt][2] = zA[nt][3] = 0.0f;
            zB[nt][0] = zB[nt][1] = zB[nt][2] = zB[nt][3] = 0.0f;
        }
        wA[0] = wA[1] = wA[2] = wA[3] = 0.0f;
        wB[0] = wB[1] = wB[2] = wB[3] = 0.0f;

        #pragma unroll
        for (int s = 0; s < 4; s++) {
            uint32_t a0h = pkhf(ex2f(cA[2*s][0]   - mgA), ex2f(cA[2*s][1]   - mgA));
            uint32_t a1h = pkhf(ex2f(cA[2*s][2]   - m8A), ex2f(cA[2*s][3]   - m8A));
            uint32_t a2h = pkhf(ex2f(cA[2*s+1][0] - mgA), ex2f(cA[2*s+1][1] - mgA));
            uint32_t a3h = pkhf(ex2f(cA[2*s+1][2] - m8A), ex2f(cA[2*s+1][3] - m8A));
            uint32_t b0h = pkhf(ex2f(cB[2*s][0]   - mgB), ex2f(cB[2*s][1]   - mgB));
            uint32_t b1h = pkhf(ex2f(cB[2*s][2]   - m8B), ex2f(cB[2*s][3]   - m8B));
            uint32_t b2h = pkhf(ex2f(cB[2*s+1][0] - mgB), ex2f(cB[2*s+1][1] - mgB));
            uint32_t b3h = pkhf(ex2f(cB[2*s+1][2] - m8B), ex2f(cB[2*s+1][3] - m8B));

            mma16(wA, a0h, a1h, a2h, a3h, onesb, onesb);
            mma16(wB, b0h, b1h, b2h, b3h, onesb, onesb);

            #pragma unroll
            for (int nt = 0; nt < 2; nt++) {
                uint4 P = sPB[((s * 2 + nt) * 8 + g) * 4 + q];
                mma16(zA[nt], a0h, a1h, a2h, a3h, P.x, P.y);
                mma16(zA[nt], a0h, a1h, a2h, a3h, P.z, P.w);
                mma16(zB[nt], b0h, b1h, b2h, b3h, P.x, P.y);
                mma16(zB[nt], b0h, b1h, b2h, b3h, P.z, P.w);
            }
        }

        // ---- broadcast denominators from q=0 (col 0) across each quad ----
        const float igA = rcpf(__shfl_sync(0xffffffffu, wA[0], base));
        const float i8A = rcpf(__shfl_sync(0xffffffffu, wA[2], base));
        const float igB = rcpf(__shfl_sync(0xffffffffu, wB[0], base));
        const float i8B = rcpf(__shfl_sync(0xffffffffu, wB[2], base));

        // ---- normalize + float4 stores (output-permuted: cols 4q..4q+3) ----
        const size_t vA  = (size_t)chunk * 128 + lA;
        *reinterpret_cast<float4*>(out + (vA)      * DVEC + 4 * q) =
            make_float4(zA[0][0] * igA, zA[0][1] * igA, zA[1][0] * igA, zA[1][1] * igA);
        *reinterpret_cast<float4*>(out + (vA + 8)  * DVEC + 4 * q) =
            make_float4(zA[0][2] * i8A, zA[0][3] * i8A, zA[1][2] * i8A, zA[1][3] * i8A);
        *reinterpret_cast<float4*>(out + (vA + 16) * DVEC + 4 * q) =
            make_float4(zB[0][0] * igB, zB[0][1] * igB, zB[1][0] * igB, zB[1][1] * igB);
        *reinterpret_cast<float4*>(out + (vA + 24) * DVEC + 4 * q) =
            make_float4(zB[0][2] * i8B, zB[0][3] * i8B, zB[1][2] * i8B, zB[1][3] * i8B);
    }
}

extern "C" void kernel_launch(void* const* d_in, const int* in_sizes, int n_in,
                              void* d_out, int out_size) {
    const float* x   = (const float*)d_in[0];   // (64,8,32,32,16) f32
    const float* ref = (const float*)d_in[1];   // (64,16) f32
    float* out = (float*)d_out;

    // NCHUNK * 128 vectors = 524288 = nvec (fixed shape per metadata).
    stq_kernel<<<NBLK, TPB>>>(x, ref, out);
}

// round 17
// speedup vs baseline: 1.0894x; 1.0894x over previous
#include <cuda_runtime.h>
#include <cstdint>

// soft_to_hard_quantize via fp16 tensor cores (mma.m16n8k16).
// R17 = R15 (best: persistent grid-stride, direct LDG) + PER-WARP register
// prefetch: each iteration consumes the x float4s loaded during the previous
// iteration and immediately issues next-chunk LDG.128s, hiding DRAM latency
// under ~2000 cycles of MMA/softmax work. No barriers, warps stay decoupled
// (the R16 smem pipeline's block-wide syncs were a regression).
//
// logit[v][m] = 14.4269504*dot(x_v, r_m) - 7.2134752*||r_m||^2   (log2 domain)
// e = exp2(logit - rowmax);  z_v = sum_m e*r_m / sum_m e

#define TPB    128    // 4 warps/block, 2 tiles (32 vectors) per warp-iteration
#define DVEC   16
#define NCHUNK 4096   // tile-pair chunks (each chunk = 128 vectors)
#define NBLK   760    // 152 SMs x 4-5 CTAs -> one resident wave

__device__ __forceinline__ uint32_t pkhf(float lo_elem, float hi_elem) {
    uint32_t r;
    asm("cvt.rn.f16x2.f32 %0, %1, %2;" : "=r"(r) : "f"(hi_elem), "f"(lo_elem));
    return r;
}
__device__ __forceinline__ float hf0(uint32_t u) {
    float f;
    asm("{ .reg .b16 l, h; mov.b32 {l, h}, %1; cvt.f32.f16 %0, l; }" : "=f"(f) : "r"(u));
    return f;
}
__device__ __forceinline__ float hf1(uint32_t u) {
    float f;
    asm("{ .reg .b16 l, h; mov.b32 {l, h}, %1; cvt.f32.f16 %0, h; }" : "=f"(f) : "r"(u));
    return f;
}
__device__ __forceinline__ float ex2f(float x) {
    float r; asm("ex2.approx.ftz.f32 %0, %1;" : "=f"(r) : "f"(x)); return r;
}
__device__ __forceinline__ float rcpf(float x) {
    float r; asm("rcp.approx.ftz.f32 %0, %1;" : "=f"(r) : "f"(x)); return r;
}
__device__ __forceinline__ void mma16(float c[4],
                                      uint32_t a0, uint32_t a1, uint32_t a2, uint32_t a3,
                                      uint32_t b0, uint32_t b1) {
    asm volatile(
        "mma.sync.aligned.m16n8k16.row.col.f32.f16.f16.f32 "
        "{%0,%1,%2,%3}, {%4,%5,%6,%7}, {%8,%9}, {%0,%1,%2,%3};"
        : "+f"(c[0]), "+f"(c[1]), "+f"(c[2]), "+f"(c[3])
        : "r"(a0), "r"(a1), "r"(a2), "r"(a3), "r"(b0), "r"(b1));
}
__device__ __forceinline__ uint4 split4(float v0, float v1, float v2, float v3) {
    uint4 r;
    r.x = pkhf(v0, v1);
    r.y = pkhf(v2, v3);
    r.z = pkhf(v0 - hf0(r.x), v1 - hf1(r.x));
    r.w = pkhf(v2 - hf0(r.y), v3 - hf1(r.y));
    return r;
}

__global__ __launch_bounds__(TPB, 4)
void stq_kernel(const float* __restrict__ x,
                const float* __restrict__ ref,
                float* __restrict__ out) {
    // Codebook tables, built ONCE per persistent block.
    __shared__ __align__(16) uint4 sP1[256];
    __shared__ __align__(16) uint4 sPB[256];
    __shared__ float2 sB2[32];

    const int tid = threadIdx.x;

    #pragma unroll
    for (int i = tid; i < 256; i += TPB) {
        {   // pass-1 entry (m, qq): k-slots {2q,2q+1,2q+8,2q+9} <- phys {4q..4q+3}
            const int m = i >> 2, qq = i & 3;
            const float S = 14.426950408889634f;   // 10*log2(e)
            const float4 b = *reinterpret_cast<const float4*>(ref + m * DVEC + 4 * qq);
            sP1[i] = split4(S * b.x, S * b.y, S * b.z, S * b.w);
        }
        {   // pass-2 entry (s, nt, gg, qq): output col J(g,nt)=4*(g>>1)+2*nt+(g&1)
            const int qq = i & 3, gg = (i >> 2) & 7, nt = (i >> 5) & 1, s = i >> 6;
            const int j = 4 * (gg >> 1) + 2 * nt + (gg & 1);
            sPB[i] = split4(ref[(16 * s + 2 * qq) * DVEC + j],
                            ref[(16 * s + 2 * qq + 1) * DVEC + j],
                            ref[(16 * s + 2 * qq + 8) * DVEC + j],
                            ref[(16 * s + 2 * qq + 9) * DVEC + j]);
        }
    }
    if (tid < 32) {  // bias pairs (t, qq)
        const int t = tid >> 2, qq = tid & 3;
        const int m0 = 8 * t + 2 * qq, m1 = m0 + 1;
        float s0 = 0.0f, s1 = 0.0f;
        #pragma unroll
        for (int i = 0; i < DVEC; i += 4) {
            const float4 a = *reinterpret_cast<const float4*>(ref + m0 * DVEC + i);
            const float4 b = *reinterpret_cast<const float4*>(ref + m1 * DVEC + i);
            s0 = fmaf(a.x, a.x, fmaf(a.y, a.y, fmaf(a.z, a.z, fmaf(a.w, a.w, s0))));
            s1 = fmaf(b.x, b.x, fmaf(b.y, b.y, fmaf(b.z, b.z, fmaf(b.w, b.w, s1))));
        }
        sB2[tid] = make_float2(-7.2134752044448169f * s0,
                               -7.2134752044448169f * s1);
    }
    __syncthreads();

    const int warp = tid >> 5;
    const int lane = tid & 31;
    const int g = lane >> 2;     // groupID
    const int q = lane & 3;      // threadID in group
    const int base = lane & 28;
    const uint32_t onesb = (g == 0) ? 0x3C003C00u : 0u;   // fp16 1.0 pair, n=0 col

    // Per-warp x addresses: chunk c, rows (warp*32 + g + {0,8,16,24}), col 4q.
    const size_t rowA = (size_t)(warp * 32 + g);

    // ---- prologue: load first chunk's float4s into registers ----
    float4 xr0, xr1, xr2, xr3;
    {
        const float* p = x + ((size_t)blockIdx.x * 128 + rowA) * DVEC + 4 * q;
        xr0 = *reinterpret_cast<const float4*>(p);
        xr1 = *reinterpret_cast<const float4*>(p + 8  * DVEC);
        xr2 = *reinterpret_cast<const float4*>(p + 16 * DVEC);
        xr3 = *reinterpret_cast<const float4*>(p + 24 * DVEC);
    }

    for (int chunk = blockIdx.x; chunk < NCHUNK; chunk += NBLK) {
        // ---- split prefetched registers into fp16 fragments ----
        uint32_t ahA[4], alA[4], ahB[4], alB[4];
        ahA[0] = pkhf(xr0.x, xr0.y); alA[0] = pkhf(xr0.x - hf0(ahA[0]), xr0.y - hf1(ahA[0]));
        ahA[2] = pkhf(xr0.z, xr0.w); alA[2] = pkhf(xr0.z - hf0(ahA[2]), xr0.w - hf1(ahA[2]));
        ahA[1] = pkhf(xr1.x, xr1.y); alA[1] = pkhf(xr1.x - hf0(ahA[1]), xr1.y - hf1(ahA[1]));
        ahA[3] = pkhf(xr1.z, xr1.w); alA[3] = pkhf(xr1.z - hf0(ahA[3]), xr1.w - hf1(ahA[3]));
        ahB[0] = pkhf(xr2.x, xr2.y); alB[0] = pkhf(xr2.x - hf0(ahB[0]), xr2.y - hf1(ahB[0]));
        ahB[2] = pkhf(xr2.z, xr2.w); alB[2] = pkhf(xr2.z - hf0(ahB[2]), xr2.w - hf1(ahB[2]));
        ahB[1] = pkhf(xr3.x, xr3.y); alB[1] = pkhf(xr3.x - hf0(ahB[1]), xr3.y - hf1(ahB[1]));
        ahB[3] = pkhf(xr3.z, xr3.w); alB[3] = pkhf(xr3.z - hf0(ahB[3]), xr3.w - hf1(ahB[3]));

        // ---- issue next-chunk loads NOW (land during compute below) ----
        {
            const int nc = chunk + NBLK;
            if (nc < NCHUNK) {
                const float* p = x + ((size_t)nc * 128 + rowA) * DVEC + 4 * q;
                xr0 = *reinterpret_cast<const float4*>(p);
                xr1 = *reinterpret_cast<const float4*>(p + 8  * DVEC);
                xr2 = *reinterpret_cast<const float4*>(p + 16 * DVEC);
                xr3 = *reinterpret_cast<const float4*>(p + 24 * DVEC);
            }
        }

        // ---- Pass 1: logits; bias pre-loaded into accumulators ----
        float cA[8][4], cB[8][4];
        #pragma unroll
        for (int t = 0; t < 8; t++) {
            float2 bb = sB2[t * 4 + q];
            cA[t][0] = bb.x; cA[t][1] = bb.y; cA[t][2] = bb.x; cA[t][3] = bb.y;
            cB[t][0] = bb.x; cB[t][1] = bb.y; cB[t][2] = bb.x; cB[t][3] = bb.y;
        }
        #pragma unroll
        for (int t = 0; t < 8; t++) {
            uint4 P = sP1[(8 * t + g) * 4 + q];
            mma16(cA[t], ahA[0], ahA[1], ahA[2], ahA[3], P.x, P.y);
            mma16(cA[t], ahA[0], ahA[1], ahA[2], ahA[3], P.z, P.w);
            mma16(cA[t], alA[0], alA[1], alA[2], alA[3], P.x, P.y);
            mma16(cB[t], ahB[0], ahB[1], ahB[2], ahB[3], P.x, P.y);
            mma16(cB[t], ahB[0], ahB[1], ahB[2], ahB[3], P.z, P.w);
            mma16(cB[t], alB[0], alB[1], alB[2], alB[3], P.x, P.y);
        }

        // ---- row maxes ----
        float mgA = fmaxf(cA[0][0], cA[0][1]), m8A = fmaxf(cA[0][2], cA[0][3]);
        float mgB = fmaxf(cB[0][0], cB[0][1]), m8B = fmaxf(cB[0][2], cB[0][3]);
        #pragma unroll
        for (int t = 1; t < 8; t++) {
            mgA = fmaxf(mgA, fmaxf(cA[t][0], cA[t][1]));
            m8A = fmaxf(m8A, fmaxf(cA[t][2], cA[t][3]));
            mgB = fmaxf(mgB, fmaxf(cB[t][0], cB[t][1]));
            m8B = fmaxf(m8B, fmaxf(cB[t][2], cB[t][3]));
        }
        mgA = fmaxf(mgA, __shfl_xor_sync(0xffffffffu, mgA, 1));
        mgA = fmaxf(mgA, __shfl_xor_sync(0xffffffffu, mgA, 2));
        m8A = fmaxf(m8A, __shfl_xor_sync(0xffffffffu, m8A, 1));
        m8A = fmaxf(m8A, __shfl_xor_sync(0xffffffffu, m8A, 2));
        mgB = fmaxf(mgB, __shfl_xor_sync(0xffffffffu, mgB, 1));
        mgB = fmaxf(mgB, __shfl_xor_sync(0xffffffffu, mgB, 2));
        m8B = fmaxf(m8B, __shfl_xor_sync(0xffffffffu, m8B, 1));
        m8B = fmaxf(m8B, __shfl_xor_sync(0xffffffffu, m8B, 2));

        // ---- Pass 2: exp -> fp16 ONCE; z MMAs + ones-column denominator ----
        float zA[2][4], zB[2][4], wA[4], wB[4];
        #pragma unroll
        for (int nt = 0; nt < 2; nt++) {
            zA[nt][0] = zA[nt][1] = zA[nt][2] = zA[nt][3] = 0.0f;
            zB[nt][0] = zB[nt][1] = zB[nt][2] = zB[nt][3] = 0.0f;
        }
        wA[0] = wA[1] = wA[2] = wA[3] = 0.0f;
        wB[0] = wB[1] = wB[2] = wB[3] = 0.0f;

        #pragma unroll
        for (int s = 0; s < 4; s++) {
            uint32_t a0h = pkhf(ex2f(cA[2*s][0]   - mgA), ex2f(cA[2*s][1]   - mgA));
            uint32_t a1h = pkhf(ex2f(cA[2*s][2]   - m8A), ex2f(cA[2*s][3]   - m8A));
            uint32_t a2h = pkhf(ex2f(cA[2*s+1][0] - mgA), ex2f(cA[2*s+1][1] - mgA));
            uint32_t a3h = pkhf(ex2f(cA[2*s+1][2] - m8A), ex2f(cA[2*s+1][3] - m8A));
            uint32_t b0h = pkhf(ex2f(cB[2*s][0]   - mgB), ex2f(cB[2*s][1]   - mgB));
            uint32_t b1h = pkhf(ex2f(cB[2*s][2]   - m8B), ex2f(cB[2*s][3]   - m8B));
            uint32_t b2h = pkhf(ex2f(cB[2*s+1][0] - mgB), ex2f(cB[2*s+1][1] - mgB));
            uint32_t b3h = pkhf(ex2f(cB[2*s+1][2] - m8B), ex2f(cB[2*s+1][3] - m8B));

            mma16(wA, a0h, a1h, a2h, a3h, onesb, onesb);
            mma16(wB, b0h, b1h, b2h, b3h, onesb, onesb);

            #pragma unroll
            for (int nt = 0; nt < 2; nt++) {
                uint4 P = sPB[((s * 2 + nt) * 8 + g) * 4 + q];
                mma16(zA[nt], a0h, a1h, a2h, a3h, P.x, P.y);
                mma16(zA[nt], a0h, a1h, a2h, a3h, P.z, P.w);
                mma16(zB[nt], b0h, b1h, b2h, b3h, P.x, P.y);
                mma16(zB[nt], b0h, b1h, b2h, b3h, P.z, P.w);
            }
        }

        // ---- broadcast denominators from q=0 (col 0) across each quad ----
        const float igA = rcpf(__shfl_sync(0xffffffffu, wA[0], base));
        const float i8A = rcpf(__shfl_sync(0xffffffffu, wA[2], base));
        const float igB = rcpf(__shfl_sync(0xffffffffu, wB[0], base));
        const float i8B = rcpf(__shfl_sync(0xffffffffu, wB[2], base));

        // ---- normalize + float4 stores (output-permuted: cols 4q..4q+3) ----
        const size_t vA = (size_t)chunk * 128 + rowA;
        *reinterpret_cast<float4*>(out + (vA)      * DVEC + 4 * q) =
            make_float4(zA[0][0] * igA, zA[0][1] * igA, zA[1][0] * igA, zA[1][1] * igA);
        *reinterpret_cast<float4*>(out + (vA + 8)  * DVEC + 4 * q) =
            make_float4(zA[0][2] * i8A, zA[0][3] * i8A, zA[1][2] * i8A, zA[1][3] * i8A);
        *reinterpret_cast<float4*>(out + (vA + 16) * DVEC + 4 * q) =
            make_float4(zB[0][0] * igB, zB[0][1] * igB, zB[1][0] * igB, zB[1][1] * igB);
        *reinterpret_cast<float4*>(out + (vA + 24) * DVEC + 4 * q) =
            make_float4(zB[0][2] * i8B, zB[0][3] * i8B, zB[1][2] * i8B, zB[1][3] * i8B);
    }
}

extern "C" void kernel_launch(void* const* d_in, const int* in_sizes, int n_in,
                              void* d_out, int out_size) {
    const float* x   = (const float*)d_in[0];   // (64,8,32,32,16) f32
    const float* ref = (const float*)d_in[1];   // (64,16) f32
    float* out = (float*)d_out;

    // NCHUNK * 128 vectors = 524288 = nvec (fixed shape per metadata).
    stq_kernel<<<NBLK, TPB>>>(x, ref, out);
}